// round 14
// baseline (speedup 1.0000x reference)
#include <cuda_runtime.h>
#include <cuda_fp16.h>
#include <cstdint>

// 1-NN via int8 filter + exact fp32 re-rank.
//   Phase 1: q(x)=rn(21*x) int8; IMMA m16n8k32 GEMM; per (query, 32-col subtile)
//            store tmin = min (t2[n] - (2/S^2)*idot)  (no indices). err sigma~0.62
//   Phase 2: per query, exact fp32 rescan of subtiles with tmin <= gmin+8.0;
//            argmin first-min tie rule; gather Y row.

#define B_ROWS   2048
#define N_TRAIN  50000
#define N_PAD    50048        // 391 * 128
#define FEAT     256
#define OUTD     24
#define MT       128
#define NTT      391          // n tiles of 128
#define NSUB     (NTT*4)      // 1564 subtiles of 32
#define NSTRIPS  9
#define TPS      44           // ceil(391/9)
#define NSTAGES  4
#define QS       21.0f
#define INV2     (2.0f/(QS*QS))
#define MARGIN   8.0f

// smem layout (dynamic) for knn_approx
#define SM_T2    0                      // 128 floats
#define SM_A     1024                   // 2 chunks x 16384 = 32 KB resident
#define SM_B     (1024 + 2*16384)       // 33792 ; 4 stages x 32 KB ring
#define SMEM_BYTES (SM_B + NSTAGES*32768)   // 164864 <= 232448

__device__ __align__(16) int8_t g_Aq[(size_t)B_ROWS * FEAT];
__device__ __align__(16) int8_t g_Bq[(size_t)N_PAD * FEAT];
__device__ float g_t2[N_PAD];
__device__ float g_tmin[(size_t)B_ROWS * NSUB];

// ---------------- PTX helpers (base-arch legal) ----------------
__device__ __forceinline__ uint32_t smem_u32(const void* p) {
    uint32_t a;
    asm("{ .reg .u64 t; cvta.to.shared.u64 t, %1; cvt.u32.u64 %0, t; }"
        : "=r"(a) : "l"(p));
    return a;
}

#define CP_ASYNC16(dst, src) \
    asm volatile("cp.async.cg.shared.global [%0], [%1], 16;" :: "r"(dst), "l"(src) : "memory")
#define CP_COMMIT() asm volatile("cp.async.commit_group;" ::: "memory")
#define CP_WAIT2()  asm volatile("cp.async.wait_group 2;" ::: "memory")

// non-trans ldmatrix b16: with 16B k-segments of int8 rows it delivers exactly
// the IMMA s8 fragments (thread t: 4 bytes k=(t%4)*4 of its row).
#define LDSM_X4(r, addr)                                                        \
    asm volatile("ldmatrix.sync.aligned.m8n8.x4.shared.b16 {%0,%1,%2,%3}, [%4];" \
                 : "=r"((r)[0]), "=r"((r)[1]), "=r"((r)[2]), "=r"((r)[3])        \
                 : "r"(addr))

__device__ __forceinline__ void imma16832(int* d, const uint32_t* a,
                                          const uint32_t* b) {
    asm volatile(
        "mma.sync.aligned.m16n8k32.row.col.s32.s8.s8.s32 "
        "{%0,%1,%2,%3}, {%4,%5,%6,%7}, {%8,%9}, {%0,%1,%2,%3};"
        : "+r"(d[0]), "+r"(d[1]), "+r"(d[2]), "+r"(d[3])
        : "r"(a[0]), "r"(a[1]), "r"(a[2]), "r"(a[3]), "r"(b[0]), "r"(b[1]));
}

// swizzled byte offset within a 128-row x 128-byte SW128 chunk
__device__ __forceinline__ uint32_t swz(int r, int sg) {
    return (uint32_t)(r * 128 + ((sg ^ (r & 7)) << 4));
}

__device__ __forceinline__ int8_t quant(float x) {
    int q = __float2int_rn(x * QS);
    q = max(-127, min(127, q));
    return (int8_t)q;
}

// ---------------- prep: int8 quantization + t2 ----------------
__global__ void prep_query(const float* __restrict__ X) {
    int w = threadIdx.x >> 5, l = threadIdx.x & 31;
    int row = blockIdx.x * 8 + w;                    // 256*8 = 2048
    const float4* src = reinterpret_cast<const float4*>(X + (size_t)row * FEAT);
    float4 a = src[l * 2], b = src[l * 2 + 1];
    float xs[8] = {a.x, a.y, a.z, a.w, b.x, b.y, b.z, b.w};
    __align__(8) int8_t q[8];
#pragma unroll
    for (int j = 0; j < 8; j++) q[j] = quant(xs[j]);
    reinterpret_cast<uint2*>(g_Aq + (size_t)row * FEAT)[l] =
        *reinterpret_cast<uint2*>(q);
}

__global__ void prep_train(const float* __restrict__ X) {
    int w = threadIdx.x >> 5, l = threadIdx.x & 31;
    int row = blockIdx.x * 8 + w;                    // 6256*8 = 50048
    __align__(8) int8_t q[8];
    if (row < N_TRAIN) {
        const float4* src = reinterpret_cast<const float4*>(X + (size_t)row * FEAT);
        float4 a = src[l * 2], b = src[l * 2 + 1];
        float xs[8] = {a.x, a.y, a.z, a.w, b.x, b.y, b.z, b.w};
        float ss = 0.f;
#pragma unroll
        for (int j = 0; j < 8; j++) {
            ss += xs[j] * xs[j];
            q[j] = quant(xs[j]);
        }
#pragma unroll
        for (int off = 16; off; off >>= 1)
            ss += __shfl_xor_sync(0xffffffffu, ss, off);
        if (l == 0) g_t2[row] = ss;
    } else {
#pragma unroll
        for (int j = 0; j < 8; j++) q[j] = 0;
        if (l == 0) g_t2[row] = 1.0e30f;
    }
    reinterpret_cast<uint2*>(g_Bq + (size_t)row * FEAT)[l] =
        *reinterpret_cast<uint2*>(q);
}

// ---------------- phase 1: int8 GEMM + per-subtile min ----------------
__global__ void __launch_bounds__(256, 1) knn_approx() {
    extern __shared__ char smem[];
    const uint32_t sb = smem_u32(smem);
    const int tid  = threadIdx.x;
    const int wid  = tid >> 5;
    const int lane = tid & 31;
    const int warp_m = wid >> 1;          // 0..3 -> rows 32*warp_m
    const int warp_n = wid & 1;           // 0..1 -> cols 64*warp_n
    const int m0 = blockIdx.x * MT;

    const int t0 = blockIdx.y * TPS;
    int t1 = t0 + TPS; if (t1 > NTT) t1 = NTT;

    // issue full B tile t (128 rows x 256 B = 32 KB) into stage (t-t0)&3
    auto issue = [&](int t) {
        if (t < t1) {
            int n0 = t << 7;
            uint32_t bb = sb + SM_B + (uint32_t)((t - t0) & 3) * 32768u;
#pragma unroll
            for (int i = 0; i < 8; i++) {
                int idx = tid + (i << 8);          // 0..2047
                int ch = idx >> 10;                // 16B seg: chunk 0..1
                int r  = (idx >> 3) & 127;
                int sg = idx & 7;
                uint32_t dst = bb + (uint32_t)ch * 16384u + swz(r, sg);
                const int8_t* src = g_Bq + (size_t)(n0 + r) * FEAT + ch * 128 + sg * 16;
                CP_ASYNC16(dst, src);
            }
        }
        CP_COMMIT();
    };

    issue(t0); issue(t0 + 1); issue(t0 + 2);

    // resident A tile: 128 rows x 256 B, 2 SW128 chunks
    {
#pragma unroll
        for (int i = 0; i < 8; i++) {
            int idx = tid + (i << 8);
            int ch = idx >> 10;
            int r  = (idx >> 3) & 127;
            int sg = idx & 7;
            uint4 v = *reinterpret_cast<const uint4*>(
                g_Aq + (size_t)(m0 + r) * FEAT + ch * 128 + sg * 16);
            *reinterpret_cast<uint4*>(smem + SM_A + ch * 16384 + swz(r, sg)) = v;
        }
    }

    float* t2s = reinterpret_cast<float*>(smem + SM_T2);

    const int laA = lane & 15;
    const int lsA = lane >> 4;
    const int laB = (lane & 7) + ((lane >> 4) & 1) * 8;
    const int lsB = (lane >> 3) & 1;
    const uint32_t sbA = sb + SM_A;
    const uint32_t sbB = sb + SM_B;

    for (int t = t0; t < t1; t++) {
        const int n0 = t << 7;
        if (tid < 128) t2s[tid] = g_t2[n0 + tid];

        CP_WAIT2();                    // B stage for tile t landed
        __syncthreads();               // stage + t2s visible; prev reads done

        int acc[2][8][4];
#pragma unroll
        for (int mf = 0; mf < 2; mf++)
#pragma unroll
            for (int nf = 0; nf < 8; nf++)
#pragma unroll
                for (int q = 0; q < 4; q++) acc[mf][nf][q] = 0;

        const uint32_t bstage = sbB + (uint32_t)((t - t0) & 3) * 32768u;
#pragma unroll
        for (int ks = 0; ks < 8; ks++) {           // 8 x k32 = K 256
            const int ch = ks >> 2;
            const int sgp = (ks & 3) * 2;
            const uint32_t ab = sbA + (uint32_t)ch * 16384u;
            const uint32_t bb = bstage + (uint32_t)ch * 16384u;
            uint32_t a0[4], a1[4], bfr[4][4];
            {
                int r = warp_m * 32 + laA;
                LDSM_X4(a0, ab + swz(r, sgp + lsA));
                LDSM_X4(a1, ab + swz(r + 16, sgp + lsA));
            }
#pragma unroll
            for (int nfp = 0; nfp < 4; nfp++) {
                int r = warp_n * 64 + nfp * 16 + laB;
                LDSM_X4(bfr[nfp], bb + swz(r, sgp + lsB));
            }
#pragma unroll
            for (int nf = 0; nf < 8; nf++) {
                const uint32_t* bp = &bfr[nf >> 1][(nf & 1) * 2];
                imma16832(acc[0][nf], a0, bp);
                imma16832(acc[1][nf], a1, bp);
            }
        }

        // epilogue: per-row subtile minima (each warp owns 2 whole subtiles)
        const int cbase = warp_n * 64 + (lane & 3) * 2;
        float vloc[2][2][2];           // [mf][rr][sub-half]
#pragma unroll
        for (int mf = 0; mf < 2; mf++) {
#pragma unroll
            for (int rr = 0; rr < 2; rr++) {
                float v0 = 3.0e38f, v1 = 3.0e38f;
#pragma unroll
                for (int nf = 0; nf < 4; nf++) {
                    int col = cbase + nf * 8;
                    float d0 = fmaf(-INV2, (float)acc[mf][nf][rr * 2 + 0], t2s[col]);
                    float d1 = fmaf(-INV2, (float)acc[mf][nf][rr * 2 + 1], t2s[col + 1]);
                    v0 = fminf(v0, fminf(d0, d1));
                }
#pragma unroll
                for (int nf = 4; nf < 8; nf++) {
                    int col = cbase + nf * 8;
                    float d0 = fmaf(-INV2, (float)acc[mf][nf][rr * 2 + 0], t2s[col]);
                    float d1 = fmaf(-INV2, (float)acc[mf][nf][rr * 2 + 1], t2s[col + 1]);
                    v1 = fminf(v1, fminf(d0, d1));
                }
#pragma unroll
                for (int off = 1; off <= 2; off <<= 1) {
                    v0 = fminf(v0, __shfl_xor_sync(0xffffffffu, v0, off));
                    v1 = fminf(v1, __shfl_xor_sync(0xffffffffu, v1, off));
                }
                vloc[mf][rr][0] = v0;
                vloc[mf][rr][1] = v1;
            }
        }
        __syncthreads();               // stage reads done before refill
        issue(t + 3);
        if ((lane & 3) == 0) {
#pragma unroll
            for (int mf = 0; mf < 2; mf++)
#pragma unroll
                for (int rr = 0; rr < 2; rr++) {
                    int row = warp_m * 32 + mf * 16 + (lane >> 2) + rr * 8;
                    float2 w2 = make_float2(vloc[mf][rr][0], vloc[mf][rr][1]);
                    *reinterpret_cast<float2*>(
                        g_tmin + (size_t)(m0 + row) * NSUB + t * 4 + warp_n * 2) = w2;
                }
        }
    }
}

// ---------------- phase 2: exact re-rank of candidate subtiles ----------------
__global__ void __launch_bounds__(128) finalize(
    const float* __restrict__ X, const float* __restrict__ Xt,
    const float* __restrict__ Y, float* __restrict__ out) {
    const int m = blockIdx.x;
    const int tid = threadIdx.x;
    const int wid = tid >> 5;
    const int lane = tid & 31;

    __shared__ __align__(16) float s_tmin[NSUB];
    __shared__ __align__(16) float s_xq[FEAT];
    __shared__ float s_red[4];
    __shared__ float s_bv[4];
    __shared__ int   s_bi[4];
    __shared__ int   s_cand[256];
    __shared__ int   s_cnt;

    if (tid == 0) s_cnt = 0;

    // load tmin row (vectorized) + local min
    const float4* tm4 = reinterpret_cast<const float4*>(g_tmin + (size_t)m * NSUB);
    float4* st4 = reinterpret_cast<float4*>(s_tmin);
    float lmin = 3.0e38f;
    for (int i = tid; i < NSUB / 4; i += 128) {
        float4 v = tm4[i];
        st4[i] = v;
        lmin = fminf(lmin, fminf(fminf(v.x, v.y), fminf(v.z, v.w)));
    }
#pragma unroll
    for (int off = 16; off; off >>= 1)
        lmin = fminf(lmin, __shfl_xor_sync(0xffffffffu, lmin, off));
    if (lane == 0) s_red[wid] = lmin;
    for (int i = tid; i < FEAT; i += 128) s_xq[i] = X[(size_t)m * FEAT + i];
    __syncthreads();

    const float thr = fminf(fminf(s_red[0], s_red[1]),
                            fminf(s_red[2], s_red[3])) + MARGIN;

    // collect candidate subtiles
    for (int i = tid; i < NSUB; i += 128) {
        if (s_tmin[i] <= thr) {
            int pos = atomicAdd(&s_cnt, 1);
            if (pos < 256) s_cand[pos] = i;
        }
    }
    __syncthreads();
    int cnt = s_cnt; if (cnt > 256) cnt = 256;

    const float4* T4  = reinterpret_cast<const float4*>(Xt);
    const float4* xq4 = reinterpret_cast<const float4*>(s_xq);
    const float4 x0 = xq4[lane * 2];
    const float4 x1 = xq4[lane * 2 + 1];

    float bv = 3.0e38f;
    int   bi = 0x7fffffff;

    for (int c = 0; c < cnt; c++) {
        const int nb = s_cand[c] * 32 + wid * 8;
#pragma unroll 1
        for (int k = 0; k < 8; k++) {
            int n = nb + k;
            if (n >= N_TRAIN) break;
            float4 p0 = T4[(size_t)n * 64 + lane * 2];
            float4 p1 = T4[(size_t)n * 64 + lane * 2 + 1];
            float s = x0.x * p0.x;
            s = fmaf(x0.y, p0.y, s);
            s = fmaf(x0.z, p0.z, s);
            s = fmaf(x0.w, p0.w, s);
            s = fmaf(x1.x, p1.x, s);
            s = fmaf(x1.y, p1.y, s);
            s = fmaf(x1.z, p1.z, s);
            s = fmaf(x1.w, p1.w, s);
#pragma unroll
            for (int off = 16; off; off >>= 1)
                s += __shfl_xor_sync(0xffffffffu, s, off);
            float d = g_t2[n] - 2.0f * s;
            if (d < bv || (d == bv && n < bi)) { bv = d; bi = n; }
        }
    }

    if (lane == 0) { s_bv[wid] = bv; s_bi[wid] = bi; }
    __syncthreads();
    float fb = 3.0e38f;
    int   fi = 0x7fffffff;
#pragma unroll
    for (int w = 0; w < 4; w++) {
        float ov = s_bv[w]; int oi = s_bi[w];
        if (ov < fb || (ov == fb && oi < fi)) { fb = ov; fi = oi; }
    }
    if (tid < OUTD)
        out[(size_t)m * OUTD + tid] = Y[(size_t)fi * OUTD + tid];
}

// ---------------- launch ----------------
extern "C" void kernel_launch(void* const* d_in, const int* in_sizes, int n_in,
                              void* d_out, int out_size) {
    const float* x  = (const float*)d_in[0];     // [2048, 256]
    const float* Xt = (const float*)d_in[1];     // [50000, 256]
    const float* Yt = (const float*)d_in[2];     // [50000, 24]
    float* out = (float*)d_out;                  // [2048, 24]
    (void)in_sizes; (void)n_in; (void)out_size;

    cudaFuncSetAttribute(knn_approx, cudaFuncAttributeMaxDynamicSharedMemorySize,
                         SMEM_BYTES);

    prep_query<<<B_ROWS / 8, 256>>>(x);
    prep_train<<<N_PAD / 8, 256>>>(Xt);
    dim3 grid(B_ROWS / MT, NSTRIPS);
    knn_approx<<<grid, 256, SMEM_BYTES>>>();
    finalize<<<B_ROWS, 128>>>(x, Xt, Yt, out);
}

// round 16
// speedup vs baseline: 2.2926x; 2.2926x over previous
#include <cuda_runtime.h>
#include <cuda_fp16.h>
#include <cstdint>

// 1-NN via fp16 filter + exact fp32 re-rank.
//   Phase 1: single-term fp16 HMMA GEMM (K=256, f16 accumulators). Per
//     (query, 32-col subtile) store tmin = min (t2[n] - 2*cross). No indices.
//     Total filter error sigma ~0.3 (fp16 inputs + f16 accumulation).
//   Phase 2: per query, exact fp32 rescan of subtiles with tmin <= gmin+6;
//     argmin with first-min tie rule; gather Y row.

#define B_ROWS   2048
#define N_TRAIN  50000
#define N_PAD    50048        // 391 * 128
#define FEAT     256
#define OUTD     24
#define MT       128
#define NTT      391          // n tiles of 128
#define NSUB     (NTT*4)      // 1564 subtiles of 32
#define NSTRIPS  9
#define TPS      44           // ceil(391/9)
#define MARGIN   6.0f

// smem layout (dynamic) for knn_approx
#define SM_T2    0                      // 128 floats
#define SM_A     1024                   // 4 sub-chunks x 16384 = 64 KB resident
#define SM_B     (1024 + 4*16384)       // 66560 ; 2 stages x 64 KB ring
#define SMEM_BYTES (SM_B + 2*65536)     // 197632 <= 232448

__device__ __align__(16) __half g_Ah[(size_t)B_ROWS * FEAT];   // fp16(x)
__device__ __align__(16) __half g_Bh[(size_t)N_PAD * FEAT];    // fp16(t)
__device__ float g_t2[N_PAD];
__device__ float g_tmin[(size_t)B_ROWS * NSUB];

// ---------------- PTX helpers (base-arch legal) ----------------
__device__ __forceinline__ uint32_t smem_u32(const void* p) {
    uint32_t a;
    asm("{ .reg .u64 t; cvta.to.shared.u64 t, %1; cvt.u32.u64 %0, t; }"
        : "=r"(a) : "l"(p));
    return a;
}

#define CP_ASYNC16(dst, src) \
    asm volatile("cp.async.cg.shared.global [%0], [%1], 16;" :: "r"(dst), "l"(src) : "memory")
#define CP_COMMIT() asm volatile("cp.async.commit_group;" ::: "memory")
#define CP_WAIT1()  asm volatile("cp.async.wait_group 1;" ::: "memory")

// non-trans ldmatrix: for A ([M][K]) gives the A fragment; for B ([N][K],
// K contiguous) gives exactly the required col-major B fragment.
#define LDSM_X4(r, addr)                                                        \
    asm volatile("ldmatrix.sync.aligned.m8n8.x4.shared.b16 {%0,%1,%2,%3}, [%4];" \
                 : "=r"((r)[0]), "=r"((r)[1]), "=r"((r)[2]), "=r"((r)[3])        \
                 : "r"(addr))

// fp16-accumulator HMMA: D(2 regs = 4 halves) = A*B + D
__device__ __forceinline__ void mma16816h(uint32_t* d, const uint32_t* a,
                                          const uint32_t* b) {
    asm volatile(
        "mma.sync.aligned.m16n8k16.row.col.f16.f16.f16.f16 "
        "{%0,%1}, {%2,%3,%4,%5}, {%6,%7}, {%0,%1};"
        : "+r"(d[0]), "+r"(d[1])
        : "r"(a[0]), "r"(a[1]), "r"(a[2]), "r"(a[3]), "r"(b[0]), "r"(b[1]));
}

// swizzled byte offset within a 128-row x 128-byte SW128 chunk
__device__ __forceinline__ uint32_t swz(int r, int sg) {
    return (uint32_t)(r * 128 + ((sg ^ (r & 7)) << 4));
}

// ---------------- prep: fp16 conversion + t2 ----------------
__global__ void prep_query(const float* __restrict__ X) {
    int w = threadIdx.x >> 5, l = threadIdx.x & 31;
    int row = blockIdx.x * 8 + w;                    // 256*8 = 2048
    const float4* src = reinterpret_cast<const float4*>(X + (size_t)row * FEAT);
    float4 a = src[l * 2], b = src[l * 2 + 1];
    float xs[8] = {a.x, a.y, a.z, a.w, b.x, b.y, b.z, b.w};
    __align__(16) __half h[8];
#pragma unroll
    for (int j = 0; j < 8; j++) h[j] = __float2half_rn(xs[j]);
    reinterpret_cast<uint4*>(g_Ah + (size_t)row * FEAT)[l] =
        *reinterpret_cast<uint4*>(h);
}

__global__ void prep_train(const float* __restrict__ X) {
    int w = threadIdx.x >> 5, l = threadIdx.x & 31;
    int row = blockIdx.x * 8 + w;                    // 6256*8 = 50048
    __align__(16) __half h[8];
    if (row < N_TRAIN) {
        const float4* src = reinterpret_cast<const float4*>(X + (size_t)row * FEAT);
        float4 a = src[l * 2], b = src[l * 2 + 1];
        float xs[8] = {a.x, a.y, a.z, a.w, b.x, b.y, b.z, b.w};
        float ss = 0.f;
#pragma unroll
        for (int j = 0; j < 8; j++) {
            ss += xs[j] * xs[j];
            h[j] = __float2half_rn(xs[j]);
        }
#pragma unroll
        for (int off = 16; off; off >>= 1)
            ss += __shfl_xor_sync(0xffffffffu, ss, off);
        if (l == 0) g_t2[row] = ss;
    } else {
#pragma unroll
        for (int j = 0; j < 8; j++) h[j] = __ushort_as_half((unsigned short)0);
        if (l == 0) g_t2[row] = 1.0e30f;
    }
    reinterpret_cast<uint4*>(g_Bh + (size_t)row * FEAT)[l] =
        *reinterpret_cast<uint4*>(h);
}

// ---------------- phase 1: approx GEMM + per-subtile min ----------------
__global__ void __launch_bounds__(256, 1) knn_approx() {
    extern __shared__ char smem[];
    const uint32_t sb = smem_u32(smem);
    const int tid  = threadIdx.x;
    const int wid  = tid >> 5;
    const int lane = tid & 31;
    const int warp_m = wid >> 1;          // 0..3 -> rows 32*warp_m
    const int warp_n = wid & 1;           // 0..1 -> cols 64*warp_n
    const int m0 = blockIdx.x * MT;

    const int t0 = blockIdx.y * TPS;
    int t1 = t0 + TPS; if (t1 > NTT) t1 = NTT;

    const uint4* Bs = reinterpret_cast<const uint4*>(g_Bh);

    // issue full B tile t (128 rows x 256 halves = 64 KB) into stage (t-t0)&1
    auto issue = [&](int t) {
        if (t < t1) {
            int n0 = t << 7;
            uint32_t bb = sb + SM_B + (uint32_t)((t - t0) & 1) * 65536u;
#pragma unroll
            for (int i = 0; i < 16; i++) {
                int idx = tid + (i << 8);          // 0..4095
                int r = idx >> 5;                  // row 0..127
                int s = idx & 31;                  // 16B seg 0..31
                uint32_t dst = bb + (uint32_t)(s >> 3) * 16384u + swz(r, s & 7);
                const uint4* src = Bs + (size_t)(n0 + r) * 32 + s;
                CP_ASYNC16(dst, src);
            }
        }
        CP_COMMIT();
    };

    issue(t0); issue(t0 + 1);

    // resident A tile: 128 rows x 256 halves, 4 SW128 sub-chunks
    {
        const uint4* As = reinterpret_cast<const uint4*>(g_Ah);
#pragma unroll
        for (int i = 0; i < 16; i++) {
            int idx = tid + (i << 8);
            int r = idx >> 5;
            int s = idx & 31;
            uint4 v = As[(size_t)(m0 + r) * 32 + s];
            *reinterpret_cast<uint4*>(smem + SM_A + (s >> 3) * 16384 + swz(r, s & 7)) = v;
        }
    }

    float* t2s = reinterpret_cast<float*>(smem + SM_T2);

    const int laA = lane & 15;
    const int lsA = lane >> 4;
    const int laB = (lane & 7) + ((lane >> 4) & 1) * 8;
    const int lsB = (lane >> 3) & 1;
    const uint32_t sbA = sb + SM_A;
    const uint32_t sbB = sb + SM_B;

    for (int t = t0; t < t1; t++) {
        const int n0 = t << 7;
        if (tid < 128) t2s[tid] = g_t2[n0 + tid];

        CP_WAIT1();                    // B stage for tile t landed
        __syncthreads();               // stage + t2s visible; prev reads done

        uint32_t acc[2][8][2];         // f16x2 accumulators
#pragma unroll
        for (int mf = 0; mf < 2; mf++)
#pragma unroll
            for (int nf = 0; nf < 8; nf++) {
                acc[mf][nf][0] = 0u;
                acc[mf][nf][1] = 0u;
            }

        const uint32_t bstage = sbB + (uint32_t)((t - t0) & 1) * 65536u;
#pragma unroll
        for (int cc = 0; cc < 4; cc++) {
            const uint32_t ab = sbA + (uint32_t)cc * 16384u;
            const uint32_t bb = bstage + (uint32_t)cc * 16384u;
#pragma unroll
            for (int ks = 0; ks < 4; ks++) {
                uint32_t a0[4], a1[4], bfr[4][4];
                {
                    int r = warp_m * 32 + laA;
                    int sg = ks * 2 + lsA;
                    LDSM_X4(a0, ab + swz(r, sg));
                    r += 16;
                    LDSM_X4(a1, ab + swz(r, sg));
                }
#pragma unroll
                for (int nfp = 0; nfp < 4; nfp++) {
                    int r = warp_n * 64 + nfp * 16 + laB;
                    int sg = ks * 2 + lsB;
                    LDSM_X4(bfr[nfp], bb + swz(r, sg));
                }
#pragma unroll
                for (int nf = 0; nf < 8; nf++) {
                    const uint32_t* bp = &bfr[nf >> 1][(nf & 1) * 2];
                    mma16816h(acc[0][nf], a0, bp);
                    mma16816h(acc[1][nf], a1, bp);
                }
            }
        }

        // epilogue: per-row subtile minima (each warp owns 2 whole subtiles)
        const int cbase = warp_n * 64 + (lane & 3) * 2;
        float vloc[2][2][2];           // [mf][rr][sub-half]
#pragma unroll
        for (int mf = 0; mf < 2; mf++) {
#pragma unroll
            for (int rr = 0; rr < 2; rr++) {
                float v0 = 3.0e38f, v1 = 3.0e38f;
#pragma unroll
                for (int nf = 0; nf < 4; nf++) {
                    int col = cbase + nf * 8;
                    float2 p = __half22float2(
                        *reinterpret_cast<__half2*>(&acc[mf][nf][rr]));
                    float d0 = fmaf(-2.0f, p.x, t2s[col]);
                    float d1 = fmaf(-2.0f, p.y, t2s[col + 1]);
                    v0 = fminf(v0, fminf(d0, d1));
                }
#pragma unroll
                for (int nf = 4; nf < 8; nf++) {
                    int col = cbase + nf * 8;
                    float2 p = __half22float2(
                        *reinterpret_cast<__half2*>(&acc[mf][nf][rr]));
                    float d0 = fmaf(-2.0f, p.x, t2s[col]);
                    float d1 = fmaf(-2.0f, p.y, t2s[col + 1]);
                    v1 = fminf(v1, fminf(d0, d1));
                }
#pragma unroll
                for (int off = 1; off <= 2; off <<= 1) {
                    v0 = fminf(v0, __shfl_xor_sync(0xffffffffu, v0, off));
                    v1 = fminf(v1, __shfl_xor_sync(0xffffffffu, v1, off));
                }
                vloc[mf][rr][0] = v0;
                vloc[mf][rr][1] = v1;
            }
        }
        __syncthreads();               // stage reads done before refill
        issue(t + 2);
        if ((lane & 3) == 0) {
#pragma unroll
            for (int mf = 0; mf < 2; mf++)
#pragma unroll
                for (int rr = 0; rr < 2; rr++) {
                    int row = warp_m * 32 + mf * 16 + (lane >> 2) + rr * 8;
                    float2 w2 = make_float2(vloc[mf][rr][0], vloc[mf][rr][1]);
                    *reinterpret_cast<float2*>(
                        g_tmin + (size_t)(m0 + row) * NSUB + t * 4 + warp_n * 2) = w2;
                }
        }
    }
}

// ---------------- phase 2: exact re-rank of candidate subtiles ----------------
__global__ void __launch_bounds__(128) finalize(
    const float* __restrict__ X, const float* __restrict__ Xt,
    const float* __restrict__ Y, float* __restrict__ out) {
    const int m = blockIdx.x;
    const int tid = threadIdx.x;
    const int wid = tid >> 5;
    const int lane = tid & 31;

    __shared__ __align__(16) float s_tmin[NSUB];
    __shared__ __align__(16) float s_xq[FEAT];
    __shared__ float s_red[4];
    __shared__ float s_bv[4];
    __shared__ int   s_bi[4];
    __shared__ int   s_cand[256];
    __shared__ int   s_cnt;

    if (tid == 0) s_cnt = 0;

    // load tmin row (vectorized) + local min
    const float4* tm4 = reinterpret_cast<const float4*>(g_tmin + (size_t)m * NSUB);
    float4* st4 = reinterpret_cast<float4*>(s_tmin);
    float lmin = 3.0e38f;
    for (int i = tid; i < NSUB / 4; i += 128) {
        float4 v = tm4[i];
        st4[i] = v;
        lmin = fminf(lmin, fminf(fminf(v.x, v.y), fminf(v.z, v.w)));
    }
#pragma unroll
    for (int off = 16; off; off >>= 1)
        lmin = fminf(lmin, __shfl_xor_sync(0xffffffffu, lmin, off));
    if (lane == 0) s_red[wid] = lmin;
    for (int i = tid; i < FEAT; i += 128) s_xq[i] = X[(size_t)m * FEAT + i];
    __syncthreads();

    const float thr = fminf(fminf(s_red[0], s_red[1]),
                            fminf(s_red[2], s_red[3])) + MARGIN;

    // collect candidate subtiles
    for (int i = tid; i < NSUB; i += 128) {
        if (s_tmin[i] <= thr) {
            int pos = atomicAdd(&s_cnt, 1);
            if (pos < 256) s_cand[pos] = i;
        }
    }
    __syncthreads();
    int cnt = s_cnt; if (cnt > 256) cnt = 256;

    const float4* T4  = reinterpret_cast<const float4*>(Xt);
    const float4* xq4 = reinterpret_cast<const float4*>(s_xq);
    const float4 x0 = xq4[lane * 2];
    const float4 x1 = xq4[lane * 2 + 1];

    float bv = 3.0e38f;
    int   bi = 0x7fffffff;

    for (int c = 0; c < cnt; c++) {
        const int nb = s_cand[c] * 32 + wid * 8;
#pragma unroll 1
        for (int k = 0; k < 8; k++) {
            int n = nb + k;
            if (n >= N_TRAIN) break;
            float4 p0 = T4[(size_t)n * 64 + lane * 2];
            float4 p1 = T4[(size_t)n * 64 + lane * 2 + 1];
            float s = x0.x * p0.x;
            s = fmaf(x0.y, p0.y, s);
            s = fmaf(x0.z, p0.z, s);
            s = fmaf(x0.w, p0.w, s);
            s = fmaf(x1.x, p1.x, s);
            s = fmaf(x1.y, p1.y, s);
            s = fmaf(x1.z, p1.z, s);
            s = fmaf(x1.w, p1.w, s);
#pragma unroll
            for (int off = 16; off; off >>= 1)
                s += __shfl_xor_sync(0xffffffffu, s, off);
            float d = g_t2[n] - 2.0f * s;
            if (d < bv || (d == bv && n < bi)) { bv = d; bi = n; }
        }
    }

    if (lane == 0) { s_bv[wid] = bv; s_bi[wid] = bi; }
    __syncthreads();
    float fb = 3.0e38f;
    int   fi = 0x7fffffff;
#pragma unroll
    for (int w = 0; w < 4; w++) {
        float ov = s_bv[w]; int oi = s_bi[w];
        if (ov < fb || (ov == fb && oi < fi)) { fb = ov; fi = oi; }
    }
    if (tid < OUTD)
        out[(size_t)m * OUTD + tid] = Y[(size_t)fi * OUTD + tid];
}

// ---------------- launch ----------------
extern "C" void kernel_launch(void* const* d_in, const int* in_sizes, int n_in,
                              void* d_out, int out_size) {
    const float* x  = (const float*)d_in[0];     // [2048, 256]
    const float* Xt = (const float*)d_in[1];     // [50000, 256]
    const float* Yt = (const float*)d_in[2];     // [50000, 24]
    float* out = (float*)d_out;                  // [2048, 24]
    (void)in_sizes; (void)n_in; (void)out_size;

    cudaFuncSetAttribute(knn_approx, cudaFuncAttributeMaxDynamicSharedMemorySize,
                         SMEM_BYTES);

    prep_query<<<B_ROWS / 8, 256>>>(x);
    prep_train<<<N_PAD / 8, 256>>>(Xt);
    dim3 grid(B_ROWS / MT, NSTRIPS);
    knn_approx<<<grid, 256, SMEM_BYTES>>>();
    finalize<<<B_ROWS, 128>>>(x, Xt, Yt, out);
}

// round 17
// speedup vs baseline: 2.4054x; 1.0492x over previous
#include <cuda_runtime.h>
#include <cuda_fp16.h>
#include <cstdint>

// 1-NN via fp16 filter + exact fp32 re-rank.
//   Phase 1: fp16 HMMA GEMM (K=256, f16 acc), A fragments register-resident,
//     3-stage cp.async B ring. Per (query, 32-col subtile) store
//     tmin = min (t2[n] - 2*cross). Filter error sigma ~0.15.
//   Phase 2: per query, exact fp32 rescan of subtiles with tmin <= gmin+6;
//     argmin with first-min tie rule; gather Y row.

#define B_ROWS   2048
#define N_TRAIN  50000
#define N_PAD    50048        // 391 * 128
#define FEAT     256
#define OUTD     24
#define MT       128
#define NTT      391          // n tiles of 128
#define NSUB     (NTT*4)      // 1564 subtiles of 32
#define NSTRIPS  9
#define TPS      44           // ceil(391/9)
#define MARGIN   6.0f

// smem layout (dynamic) for knn_approx
#define SM_T2    0                      // 128 floats
#define SM_B     1024                   // 3 stages x 64 KB ring (stage0 doubles
                                        // as the one-time A staging area)
#define SMEM_BYTES (SM_B + 3*65536)     // 197632 <= 232448

__device__ __align__(16) __half g_Ah[(size_t)B_ROWS * FEAT];   // fp16(x)
__device__ __align__(16) __half g_Bh[(size_t)N_PAD * FEAT];    // fp16(t)
__device__ float g_t2[N_PAD];
__device__ float g_tmin[(size_t)B_ROWS * NSUB];

// ---------------- PTX helpers (base-arch legal) ----------------
__device__ __forceinline__ uint32_t smem_u32(const void* p) {
    uint32_t a;
    asm("{ .reg .u64 t; cvta.to.shared.u64 t, %1; cvt.u32.u64 %0, t; }"
        : "=r"(a) : "l"(p));
    return a;
}

#define CP_ASYNC16(dst, src) \
    asm volatile("cp.async.cg.shared.global [%0], [%1], 16;" :: "r"(dst), "l"(src) : "memory")
#define CP_COMMIT() asm volatile("cp.async.commit_group;" ::: "memory")
#define CP_WAIT1()  asm volatile("cp.async.wait_group 1;" ::: "memory")

// non-trans ldmatrix: for A ([M][K]) gives the A fragment; for B ([N][K],
// K contiguous) gives exactly the required col-major B fragment.
#define LDSM_X4(r, addr)                                                        \
    asm volatile("ldmatrix.sync.aligned.m8n8.x4.shared.b16 {%0,%1,%2,%3}, [%4];" \
                 : "=r"((r)[0]), "=r"((r)[1]), "=r"((r)[2]), "=r"((r)[3])        \
                 : "r"(addr))

// fp16-accumulator HMMA: D(2 regs = 4 halves) = A*B + D
__device__ __forceinline__ void mma16816h(uint32_t* d, const uint32_t* a,
                                          const uint32_t* b) {
    asm volatile(
        "mma.sync.aligned.m16n8k16.row.col.f16.f16.f16.f16 "
        "{%0,%1}, {%2,%3,%4,%5}, {%6,%7}, {%0,%1};"
        : "+r"(d[0]), "+r"(d[1])
        : "r"(a[0]), "r"(a[1]), "r"(a[2]), "r"(a[3]), "r"(b[0]), "r"(b[1]));
}

// swizzled byte offset within a 128-row x 128-byte SW128 chunk
__device__ __forceinline__ uint32_t swz(int r, int sg) {
    return (uint32_t)(r * 128 + ((sg ^ (r & 7)) << 4));
}

// ---------------- prep: fp16 conversion + t2 ----------------
__global__ void prep_query(const float* __restrict__ X) {
    int w = threadIdx.x >> 5, l = threadIdx.x & 31;
    int row = blockIdx.x * 8 + w;                    // 256*8 = 2048
    const float4* src = reinterpret_cast<const float4*>(X + (size_t)row * FEAT);
    float4 a = src[l * 2], b = src[l * 2 + 1];
    float xs[8] = {a.x, a.y, a.z, a.w, b.x, b.y, b.z, b.w};
    __align__(16) __half h[8];
#pragma unroll
    for (int j = 0; j < 8; j++) h[j] = __float2half_rn(xs[j]);
    reinterpret_cast<uint4*>(g_Ah + (size_t)row * FEAT)[l] =
        *reinterpret_cast<uint4*>(h);
}

__global__ void prep_train(const float* __restrict__ X) {
    int w = threadIdx.x >> 5, l = threadIdx.x & 31;
    int row = blockIdx.x * 8 + w;                    // 6256*8 = 50048
    __align__(16) __half h[8];
    if (row < N_TRAIN) {
        const float4* src = reinterpret_cast<const float4*>(X + (size_t)row * FEAT);
        float4 a = src[l * 2], b = src[l * 2 + 1];
        float xs[8] = {a.x, a.y, a.z, a.w, b.x, b.y, b.z, b.w};
        float ss = 0.f;
#pragma unroll
        for (int j = 0; j < 8; j++) {
            ss += xs[j] * xs[j];
            h[j] = __float2half_rn(xs[j]);
        }
#pragma unroll
        for (int off = 16; off; off >>= 1)
            ss += __shfl_xor_sync(0xffffffffu, ss, off);
        if (l == 0) g_t2[row] = ss;
    } else {
#pragma unroll
        for (int j = 0; j < 8; j++) h[j] = __ushort_as_half((unsigned short)0);
        if (l == 0) g_t2[row] = 1.0e30f;
    }
    reinterpret_cast<uint4*>(g_Bh + (size_t)row * FEAT)[l] =
        *reinterpret_cast<uint4*>(h);
}

// ---------------- phase 1: approx GEMM + per-subtile min ----------------
__global__ void __launch_bounds__(256, 1) knn_approx() {
    extern __shared__ char smem[];
    const uint32_t sb = smem_u32(smem);
    const int tid  = threadIdx.x;
    const int lane = tid & 31;
    const int wid  = tid >> 5;
    const int warp_m = wid >> 1;          // 0..3 -> rows 32*warp_m
    const int warp_n = wid & 1;           // 0..1 -> cols 64*warp_n
    const int m0 = blockIdx.x * MT;

    const int t0 = blockIdx.y * TPS;
    int t1 = t0 + TPS; if (t1 > NTT) t1 = NTT;

    const uint4* Bs = reinterpret_cast<const uint4*>(g_Bh);
    const uint32_t sbB = sb + SM_B;

    // ldmatrix lane coordinates
    const int laA = lane & 15;
    const int lsA = lane >> 4;
    const int laB = (lane & 7) + ((lane >> 4) & 1) * 8;
    const int lsB = (lane >> 3) & 1;

    // ---- one-time: stage A in stage-0 area, load fragments to registers ----
    uint32_t areg[2][16][4];               // [mfrag][kfrag16][4 regs] = 128 regs
    {
        const uint4* As = reinterpret_cast<const uint4*>(g_Ah);
#pragma unroll
        for (int i = 0; i < 16; i++) {
            int idx = tid + (i << 8);
            int r = idx >> 5;
            int s = idx & 31;
            uint4 v = As[(size_t)(m0 + r) * 32 + s];
            *reinterpret_cast<uint4*>(smem + SM_B + (s >> 3) * 16384 + swz(r, s & 7)) = v;
        }
        __syncthreads();
#pragma unroll
        for (int kf = 0; kf < 16; kf++) {
            const uint32_t ab = sbB + (uint32_t)(kf >> 2) * 16384u;
            int sg = (kf & 3) * 2 + lsA;
            LDSM_X4(areg[0][kf], ab + swz(warp_m * 32 + laA, sg));
            LDSM_X4(areg[1][kf], ab + swz(warp_m * 32 + 16 + laA, sg));
        }
        __syncthreads();                   // all warps done before B overwrites
    }

    // issue full B tile t (128 rows x 256 halves = 64 KB) into stage st
    auto issue = [&](int t, int st) {
        if (t < t1) {
            int n0 = t << 7;
            uint32_t bb = sbB + (uint32_t)st * 65536u;
#pragma unroll
            for (int i = 0; i < 16; i++) {
                int idx = tid + (i << 8);          // 0..4095
                int r = idx >> 5;                  // row 0..127
                int s = idx & 31;                  // 16B seg 0..31
                uint32_t dst = bb + (uint32_t)(s >> 3) * 16384u + swz(r, s & 7);
                const uint4* src = Bs + (size_t)(n0 + r) * 32 + s;
                CP_ASYNC16(dst, src);
            }
        }
        CP_COMMIT();
    };

    issue(t0, 0); issue(t0 + 1, 1);

    float* t2s = reinterpret_cast<float*>(smem + SM_T2);

    int st = 0;
    for (int t = t0; t < t1; t++) {
        const int n0 = t << 7;
        // safe: previous tile's t2s readers finished before prev end-barrier
        if (tid < 128) t2s[tid] = g_t2[n0 + tid];

        CP_WAIT1();                    // stage for tile t landed
        __syncthreads();               // stage + t2s visible to all warps
        issue(t + 2, (st + 2) % 3);    // prefetch overlapped with compute
                                       // (target stage consumed in tile t-1)

        uint32_t acc[2][8][2];         // f16x2 accumulators
#pragma unroll
        for (int mf = 0; mf < 2; mf++)
#pragma unroll
            for (int nf = 0; nf < 8; nf++) {
                acc[mf][nf][0] = 0u;
                acc[mf][nf][1] = 0u;
            }

        const uint32_t bstage = sbB + (uint32_t)st * 65536u;
#pragma unroll
        for (int kf = 0; kf < 16; kf++) {
            const uint32_t bb = bstage + (uint32_t)(kf >> 2) * 16384u;
            const int sg = (kf & 3) * 2 + lsB;
            uint32_t bfr[4][4];
#pragma unroll
            for (int nfp = 0; nfp < 4; nfp++) {
                int r = warp_n * 64 + nfp * 16 + laB;
                LDSM_X4(bfr[nfp], bb + swz(r, sg));
            }
#pragma unroll
            for (int nf = 0; nf < 8; nf++) {
                const uint32_t* bp = &bfr[nf >> 1][(nf & 1) * 2];
                mma16816h(acc[0][nf], areg[0][kf], bp);
                mma16816h(acc[1][nf], areg[1][kf], bp);
            }
        }

        // epilogue: per-row subtile minima (each warp owns 2 whole subtiles)
        const int cbase = warp_n * 64 + (lane & 3) * 2;
        float vloc[2][2][2];           // [mf][rr][sub-half]
#pragma unroll
        for (int mf = 0; mf < 2; mf++) {
#pragma unroll
            for (int rr = 0; rr < 2; rr++) {
                float v0 = 3.0e38f, v1 = 3.0e38f;
#pragma unroll
                for (int nf = 0; nf < 4; nf++) {
                    int col = cbase + nf * 8;
                    float2 p = __half22float2(
                        *reinterpret_cast<__half2*>(&acc[mf][nf][rr]));
                    float d0 = fmaf(-2.0f, p.x, t2s[col]);
                    float d1 = fmaf(-2.0f, p.y, t2s[col + 1]);
                    v0 = fminf(v0, fminf(d0, d1));
                }
#pragma unroll
                for (int nf = 4; nf < 8; nf++) {
                    int col = cbase + nf * 8;
                    float2 p = __half22float2(
                        *reinterpret_cast<__half2*>(&acc[mf][nf][rr]));
                    float d0 = fmaf(-2.0f, p.x, t2s[col]);
                    float d1 = fmaf(-2.0f, p.y, t2s[col + 1]);
                    v1 = fminf(v1, fminf(d0, d1));
                }
#pragma unroll
                for (int off = 1; off <= 2; off <<= 1) {
                    v0 = fminf(v0, __shfl_xor_sync(0xffffffffu, v0, off));
                    v1 = fminf(v1, __shfl_xor_sync(0xffffffffu, v1, off));
                }
                vloc[mf][rr][0] = v0;
                vloc[mf][rr][1] = v1;
            }
        }
        if ((lane & 3) == 0) {
#pragma unroll
            for (int mf = 0; mf < 2; mf++)
#pragma unroll
                for (int rr = 0; rr < 2; rr++) {
                    int row = warp_m * 32 + mf * 16 + (lane >> 2) + rr * 8;
                    float2 w2 = make_float2(vloc[mf][rr][0], vloc[mf][rr][1]);
                    *reinterpret_cast<float2*>(
                        g_tmin + (size_t)(m0 + row) * NSUB + t * 4 + warp_n * 2) = w2;
                }
        }
        __syncthreads();               // t2s reads done before next tile's write
        st = (st + 1) % 3;
    }
}

// ---------------- phase 2: exact re-rank of candidate subtiles ----------------
__global__ void __launch_bounds__(128) finalize(
    const float* __restrict__ X, const float* __restrict__ Xt,
    const float* __restrict__ Y, float* __restrict__ out) {
    const int m = blockIdx.x;
    const int tid = threadIdx.x;
    const int wid = tid >> 5;
    const int lane = tid & 31;

    __shared__ __align__(16) float s_tmin[NSUB];
    __shared__ __align__(16) float s_xq[FEAT];
    __shared__ float s_red[4];
    __shared__ float s_bv[4];
    __shared__ int   s_bi[4];
    __shared__ int   s_cand[256];
    __shared__ int   s_cnt;

    if (tid == 0) s_cnt = 0;

    // load tmin row (vectorized) + local min
    const float4* tm4 = reinterpret_cast<const float4*>(g_tmin + (size_t)m * NSUB);
    float4* st4 = reinterpret_cast<float4*>(s_tmin);
    float lmin = 3.0e38f;
    for (int i = tid; i < NSUB / 4; i += 128) {
        float4 v = tm4[i];
        st4[i] = v;
        lmin = fminf(lmin, fminf(fminf(v.x, v.y), fminf(v.z, v.w)));
    }
#pragma unroll
    for (int off = 16; off; off >>= 1)
        lmin = fminf(lmin, __shfl_xor_sync(0xffffffffu, lmin, off));
    if (lane == 0) s_red[wid] = lmin;
    for (int i = tid; i < FEAT; i += 128) s_xq[i] = X[(size_t)m * FEAT + i];
    __syncthreads();

    const float thr = fminf(fminf(s_red[0], s_red[1]),
                            fminf(s_red[2], s_red[3])) + MARGIN;

    // collect candidate subtiles
    for (int i = tid; i < NSUB; i += 128) {
        if (s_tmin[i] <= thr) {
            int pos = atomicAdd(&s_cnt, 1);
            if (pos < 256) s_cand[pos] = i;
        }
    }
    __syncthreads();
    int cnt = s_cnt; if (cnt > 256) cnt = 256;

    const float4* T4  = reinterpret_cast<const float4*>(Xt);
    const float4* xq4 = reinterpret_cast<const float4*>(s_xq);
    const float4 x0 = xq4[lane * 2];
    const float4 x1 = xq4[lane * 2 + 1];

    float bv = 3.0e38f;
    int   bi = 0x7fffffff;

    for (int c = 0; c < cnt; c++) {
        const int nb = s_cand[c] * 32 + wid * 8;
#pragma unroll
        for (int g = 0; g < 2; g++) {
            const int base = nb + g * 4;
            float s4[4];
#pragma unroll
            for (int j = 0; j < 4; j++) {
                int n = base + j;
                int nn = (n < N_TRAIN) ? n : 0;       // clamp, discard below
                float4 p0 = T4[(size_t)nn * 64 + lane * 2];
                float4 p1 = T4[(size_t)nn * 64 + lane * 2 + 1];
                float s = x0.x * p0.x;
                s = fmaf(x0.y, p0.y, s);
                s = fmaf(x0.z, p0.z, s);
                s = fmaf(x0.w, p0.w, s);
                s = fmaf(x1.x, p1.x, s);
                s = fmaf(x1.y, p1.y, s);
                s = fmaf(x1.z, p1.z, s);
                s = fmaf(x1.w, p1.w, s);
                s4[j] = s;
            }
#pragma unroll
            for (int off = 16; off; off >>= 1) {
#pragma unroll
                for (int j = 0; j < 4; j++)
                    s4[j] += __shfl_xor_sync(0xffffffffu, s4[j], off);
            }
#pragma unroll
            for (int j = 0; j < 4; j++) {
                int n = base + j;
                float d = (n < N_TRAIN) ? (g_t2[n] - 2.0f * s4[j]) : 3.0e38f;
                if (d < bv || (d == bv && n < bi)) { bv = d; bi = n; }
            }
        }
    }

    if (lane == 0) { s_bv[wid] = bv; s_bi[wid] = bi; }
    __syncthreads();
    float fb = 3.0e38f;
    int   fi = 0x7fffffff;
#pragma unroll
    for (int w = 0; w < 4; w++) {
        float ov = s_bv[w]; int oi = s_bi[w];
        if (ov < fb || (ov == fb && oi < fi)) { fb = ov; fi = oi; }
    }
    if (tid < OUTD)
        out[(size_t)m * OUTD + tid] = Y[(size_t)fi * OUTD + tid];
}

// ---------------- launch ----------------
extern "C" void kernel_launch(void* const* d_in, const int* in_sizes, int n_in,
                              void* d_out, int out_size) {
    const float* x  = (const float*)d_in[0];     // [2048, 256]
    const float* Xt = (const float*)d_in[1];     // [50000, 256]
    const float* Yt = (const float*)d_in[2];     // [50000, 24]
    float* out = (float*)d_out;                  // [2048, 24]
    (void)in_sizes; (void)n_in; (void)out_size;

    cudaFuncSetAttribute(knn_approx, cudaFuncAttributeMaxDynamicSharedMemorySize,
                         SMEM_BYTES);

    prep_query<<<B_ROWS / 8, 256>>>(x);
    prep_train<<<N_PAD / 8, 256>>>(Xt);
    dim3 grid(B_ROWS / MT, NSTRIPS);
    knn_approx<<<grid, 256, SMEM_BYTES>>>();
    finalize<<<B_ROWS, 128>>>(x, Xt, Yt, out);
}